// round 3
// baseline (speedup 1.0000x reference)
#include <cuda_runtime.h>
#include <cstddef>

// Problem constants
#define BATCH 8
#define TSEQ  1024
#define DDIM  384
#define DLANG 768
#define HID   512

#define NB 128          // grid size: guaranteed single wave on 148 SMs
#define NTHR 256

// Scratch + barrier state (allocation-free rule: __device__ globals)
__device__ float g_buf0[BATCH * HID];
__device__ float g_buf1[BATCH * HID];
__device__ float g_f[BATCH * DDIM];
__device__ unsigned g_barrier[8];   // zeroed each launch via captured cudaMemsetAsync

// ---------------------------------------------------------------------------
// Grid barrier: monotonic per-phase counters, reset by memset before launch.
// Safe: grid (128 blocks) is strictly one wave -> all blocks co-resident.
// ---------------------------------------------------------------------------
__device__ __forceinline__ void grid_barrier(int phase) {
    __syncthreads();
    if (threadIdx.x == 0) {
        __threadfence();                       // publish this block's writes
        atomicAdd(&g_barrier[phase], 1u);
        volatile unsigned* p = &g_barrier[phase];
        while (*p < NB) { __nanosleep(32); }
        __threadfence();                       // acquire others' writes
    }
    __syncthreads();
}

// ---------------------------------------------------------------------------
// One GEMV phase inside the fused kernel.
// Tasks: B * (N/32) blocks; block = 8 k-slices x 32 j columns.
// out[b, j] = sum_i in[b,i] * W[i*N + j] + bias[j]
// ---------------------------------------------------------------------------
template <int K, int N>
__device__ __forceinline__ void gemv_phase(const float* __restrict__ in,
                                           const float* __restrict__ W,
                                           const float* __restrict__ bias,
                                           float* __restrict__ out,
                                           float* sin, float (*spart)[32]) {
    constexpr int NTASK = BATCH * (N / 32);
    const int task = blockIdx.x;
    if (task < NTASK) {
        const int b  = task / (N / 32);
        const int jt = task % (N / 32);
        const int jbase = jt * 32;

        const float* inb = in + b * K;
        for (int i = threadIdx.x; i < K; i += NTHR) sin[i] = inb[i];
        __syncthreads();

        const int ks = threadIdx.x >> 5;   // 0..7
        const int jj = threadIdx.x & 31;
        const int j = jbase + jj;
        constexpr int KS = K / 8;

        float acc = 0.0f;
        const float* Wp = W + (size_t)(ks * KS) * N + j;
        const float* sp = sin + ks * KS;
#pragma unroll 8
        for (int i = 0; i < KS; ++i) {
            acc += sp[i] * Wp[(size_t)i * N];
        }
        spart[ks][jj] = acc;
        __syncthreads();

        if (threadIdx.x < 32) {
            float s = bias[j];
#pragma unroll
            for (int k = 0; k < 8; ++k) s += spart[k][jj];
            out[b * N + j] = s;
        }
        __syncthreads();   // smem reuse safety before next phase reloads sin
    }
}

// ---------------------------------------------------------------------------
// Fused kernel: 4 GEMV phases + residual broadcast add, grid barriers between.
//
// Math note: language is broadcast along T, so k/v are identical for all key
// positions; softmax over a constant row is exactly uniform 1/T and ctx == v.
// The Q path and the T x T attention cancel analytically:
//   f[b] = (((language[b] Wv + bv) Wv2 + bv2) Wo + bo) Wout + bout
//   out[b,t,:] = state[b,t,:] + f[b,:]
// ---------------------------------------------------------------------------
__global__ void __launch_bounds__(NTHR, 1)
fused_cma_kernel(const float* __restrict__ state,
                 const float* __restrict__ language,
                 const float* __restrict__ Wv,  const float* __restrict__ bv,
                 const float* __restrict__ Wv2, const float* __restrict__ bv2,
                 const float* __restrict__ Wo,  const float* __restrict__ bo,
                 const float* __restrict__ Wout,const float* __restrict__ bout,
                 float* __restrict__ out) {
    __shared__ float sin[DLANG];          // max K
    __shared__ float spart[8][32];

    gemv_phase<DLANG, HID>(language, Wv,   bv,   g_buf0, sin, spart);
    grid_barrier(0);
    gemv_phase<HID,   HID>(g_buf0,   Wv2,  bv2,  g_buf1, sin, spart);
    grid_barrier(1);
    gemv_phase<HID,   HID>(g_buf1,   Wo,   bo,   g_buf0, sin, spart);
    grid_barrier(2);
    gemv_phase<HID,  DDIM>(g_buf0,   Wout, bout, g_f,    sin, spart);
    grid_barrier(3);

    // ---- Residual broadcast add ----
    // 128 blocks, 16 blocks per batch, 64 rows (of 384 floats) per block.
    const int b  = blockIdx.x >> 4;           // /16
    const int t0 = (blockIdx.x & 15) * 64;

    __shared__ float4 fsh[DDIM / 4];          // 96
    if (threadIdx.x < DDIM / 4) {
        fsh[threadIdx.x] = reinterpret_cast<const float4*>(g_f + b * DDIM)[threadIdx.x];
    }
    __syncthreads();

    const size_t base = ((size_t)b * TSEQ + t0) * DDIM;
    const float4* sp = reinterpret_cast<const float4*>(state + base);
    float4* op = reinterpret_cast<float4*>(out + base);

    // 64 rows * 96 float4 = 6144 float4 per block -> 24 per thread
#pragma unroll
    for (int it = 0; it < 24; ++it) {
        int p = threadIdx.x + it * NTHR;      // 0..6143
        int dq = p % (DDIM / 4);
        float4 s = sp[p];
        float4 fv = fsh[dq];
        s.x += fv.x; s.y += fv.y; s.z += fv.z; s.w += fv.w;
        op[p] = s;
    }
}

// ---------------------------------------------------------------------------
// Inputs (metadata order):
//  0 state [B,T,D]   1 language [B,DL]
//  2 Wq 3 bq 4 Wk 5 bk 6 Wv 7 bv
//  8 Wq2 9 bq2 10 Wk2 11 bk2 12 Wv2 13 bv2
// 14 Wo 15 bo 16 Wout 17 bout
// Output: float32 [B,T,D]
// ---------------------------------------------------------------------------
extern "C" void kernel_launch(void* const* d_in, const int* in_sizes, int n_in,
                              void* d_out, int out_size) {
    (void)in_sizes; (void)n_in; (void)out_size;

    const float* state    = (const float*)d_in[0];
    const float* language = (const float*)d_in[1];
    const float* Wv   = (const float*)d_in[6];
    const float* bv   = (const float*)d_in[7];
    const float* Wv2  = (const float*)d_in[12];
    const float* bv2  = (const float*)d_in[13];
    const float* Wo   = (const float*)d_in[14];
    const float* bo   = (const float*)d_in[15];
    const float* Wout = (const float*)d_in[16];
    const float* bout = (const float*)d_in[17];
    float* out = (float*)d_out;

    static unsigned* barp = nullptr;
    if (!barp) {
        cudaGetSymbolAddress((void**)&barp, g_barrier);
    }

    // Reset barrier counters each launch (async memset is graph-capturable).
    cudaMemsetAsync(barp, 0, sizeof(g_barrier));

    fused_cma_kernel<<<NB, NTHR>>>(state, language,
                                   Wv, bv, Wv2, bv2, Wo, bo, Wout, bout,
                                   out);
}

// round 4
// speedup vs baseline: 1.2549x; 1.2549x over previous
#include <cuda_runtime.h>
#include <cuda_pipeline.h>
#include <cstddef>

// Problem constants
#define BATCH 8
#define TSEQ  1024
#define DDIM  384
#define DLANG 768
#define HID   512

#define NB   128        // one wave: 128 blocks x 100KB smem -> 1 block/SM
#define NTHR 256

// Scratch + barrier state (allocation-free rule: __device__ globals)
__device__ float g_buf0[BATCH * HID];
__device__ float g_buf1[BATCH * HID];
__device__ float g_f[BATCH * DDIM];
__device__ unsigned g_barrier[8];   // zeroed each launch via captured cudaMemsetAsync

// Dynamic smem layout (total 102400 B):
//   float4 st[6144]      : 98304 B  (state tile, 64 rows x 96 float4)
//   float  sin[768]      :  3072 B  (input vector for gemv; reused as f tile)
//   float  spart[256]    :  1024 B  (per-warp partials)
#define ST_F4      6144
#define SMEM_BYTES (ST_F4 * 16 + DLANG * 4 + 256 * 4)

// ---------------------------------------------------------------------------
// Grid barrier: monotonic per-phase counters (reset by memset before launch).
// Safe: grid is strictly one co-resident wave.
// ---------------------------------------------------------------------------
__device__ __forceinline__ void grid_barrier(int phase) {
    __syncthreads();
    if (threadIdx.x == 0) {
        __threadfence();                       // publish this block's writes
        atomicAdd(&g_barrier[phase], 1u);
        volatile unsigned* p = &g_barrier[phase];
        while (*p < NB) { __nanosleep(20); }
        __threadfence();                       // acquire others' writes
    }
    __syncthreads();
}

// ---------------------------------------------------------------------------
// Weight prefetch: issued BEFORE the barrier wait for the stage's input, so
// the loads are in flight while we spin. Block = task (b, jtile of 32 cols),
// warp = k-slice. Each thread holds KS = K/8 weight values in registers.
// ---------------------------------------------------------------------------
template <int K, int N>
__device__ __forceinline__ void gemv_prefetch(const float* __restrict__ W,
                                              float* wreg) {
    constexpr int NTASK = BATCH * (N / 32);
    constexpr int KS = K / 8;
    if (blockIdx.x < NTASK) {
        const int jt = blockIdx.x % (N / 32);
        const int ks = threadIdx.x >> 5;
        const int j  = jt * 32 + (threadIdx.x & 31);
        const float* Wp = W + (size_t)(ks * KS) * N + j;
#pragma unroll
        for (int i = 0; i < KS; ++i) wreg[i] = Wp[(size_t)i * N];
    }
}

// ---------------------------------------------------------------------------
// GEMV compute using prefetched weights:
// out[b, j] = sum_i in[b,i] * W[i,j] + bias[j]
// ---------------------------------------------------------------------------
template <int K, int N>
__device__ __forceinline__ void gemv_compute(const float* __restrict__ in,
                                             const float* __restrict__ bias,
                                             float* __restrict__ out,
                                             const float* wreg,
                                             float* sin, float* spart) {
    constexpr int NTASK = BATCH * (N / 32);
    constexpr int KS = K / 8;
    const bool active = blockIdx.x < NTASK;
    const int b  = blockIdx.x / (N / 32);
    const int jt = blockIdx.x % (N / 32);
    const int ks = threadIdx.x >> 5;
    const int jj = threadIdx.x & 31;

    if (active && threadIdx.x < K / 4) {
        ((float4*)sin)[threadIdx.x] =
            ((const float4*)(in + (size_t)b * K))[threadIdx.x];
    }
    __syncthreads();

    if (active) {
        const float* sp = sin + ks * KS;
        float acc = 0.0f;
#pragma unroll
        for (int i = 0; i < KS; ++i) acc += sp[i] * wreg[i];
        spart[ks * 32 + jj] = acc;
    }
    __syncthreads();

    if (active && threadIdx.x < 32) {
        const int j = jt * 32 + jj;
        float s = bias[j];
#pragma unroll
        for (int k = 0; k < 8; ++k) s += spart[k * 32 + jj];
        out[(size_t)b * N + j] = s;
    }
    // sin reuse by next phase is protected by the grid_barrier's syncthreads.
}

// ---------------------------------------------------------------------------
// Fused kernel.
//
// Math note: language is broadcast along T, so k/v are identical for all key
// positions; softmax over a constant row is exactly uniform 1/T and ctx == v.
// The Q path and the T x T attention cancel analytically:
//   f[b] = (((language[b] Wv + bv) Wv2 + bv2) Wo + bo) Wout + bout
//   out[b,t,:] = state[b,t,:] + f[b,:]
//
// Overlap structure:
//   - cp.async of this block's 96KB state tile starts at kernel entry and
//     streams during the entire GEMV chain.
//   - each stage's weight slice is register-prefetched before the barrier
//     spin for that stage's input.
// ---------------------------------------------------------------------------
extern __shared__ float4 smem_dyn[];

__global__ void __launch_bounds__(NTHR, 1)
fused_cma_kernel(const float* __restrict__ state,
                 const float* __restrict__ language,
                 const float* __restrict__ Wv,  const float* __restrict__ bv,
                 const float* __restrict__ Wv2, const float* __restrict__ bv2,
                 const float* __restrict__ Wo,  const float* __restrict__ bo,
                 const float* __restrict__ Wout,const float* __restrict__ bout,
                 float* __restrict__ out) {
    float4* st    = smem_dyn;                       // 6144 float4
    float*  sin   = (float*)(smem_dyn + ST_F4);     // 768 floats
    float*  spart = sin + DLANG;                    // 256 floats

    // ---- Kick off the state-tile stream (overlaps the whole chain) ----
    const int bres = blockIdx.x >> 4;               // residual batch
    const int t0   = (blockIdx.x & 15) * 64;
    const size_t base = ((size_t)bres * TSEQ + t0) * DDIM;
    const float4* sp_g = (const float4*)(state + base);
#pragma unroll
    for (int it = 0; it < 24; ++it) {
        const int p = threadIdx.x + it * NTHR;      // 0..6143
        __pipeline_memcpy_async(&st[p], &sp_g[p], 16);
    }
    __pipeline_commit();

    // ---- GEMV chain with register weight prefetch ----
    float wreg[DLANG / 8];                          // max KS = 96

    gemv_prefetch<DLANG, HID>(Wv, wreg);
    gemv_compute <DLANG, HID>(language, bv, g_buf0, wreg, sin, spart);

    gemv_prefetch<HID, HID>(Wv2, wreg);             // in flight during spin
    grid_barrier(0);
    gemv_compute <HID, HID>(g_buf0, bv2, g_buf1, wreg, sin, spart);

    gemv_prefetch<HID, HID>(Wo, wreg);
    grid_barrier(1);
    gemv_compute <HID, HID>(g_buf1, bo, g_buf0, wreg, sin, spart);

    gemv_prefetch<HID, DDIM>(Wout, wreg);
    grid_barrier(2);
    gemv_compute <HID, DDIM>(g_buf0, bout, g_f, wreg, sin, spart);

    grid_barrier(3);                                // f ready everywhere

    // ---- Residual broadcast add ----
    float4* fsh = (float4*)sin;                     // reuse sin region
    if (threadIdx.x < DDIM / 4) {
        fsh[threadIdx.x] =
            ((const float4*)(g_f + (size_t)bres * DDIM))[threadIdx.x];
    }
    __syncthreads();

    __pipeline_wait_prior(0);                       // this thread's tiles done

    float4* op = (float4*)(out + base);
    int dq = threadIdx.x % (DDIM / 4);              // 256 ≡ 64 (mod 96)
#pragma unroll
    for (int it = 0; it < 24; ++it) {
        const int p = threadIdx.x + it * NTHR;
        float4 s  = st[p];
        float4 fv = fsh[dq];
        s.x += fv.x; s.y += fv.y; s.z += fv.z; s.w += fv.w;
        op[p] = s;
        dq += 64; if (dq >= DDIM / 4) dq -= DDIM / 4;
    }
}

// ---------------------------------------------------------------------------
// Inputs (metadata order):
//  0 state [B,T,D]   1 language [B,DL]
//  2 Wq 3 bq 4 Wk 5 bk 6 Wv 7 bv
//  8 Wq2 9 bq2 10 Wk2 11 bk2 12 Wv2 13 bv2
// 14 Wo 15 bo 16 Wout 17 bout
// Output: float32 [B,T,D]
// ---------------------------------------------------------------------------
extern "C" void kernel_launch(void* const* d_in, const int* in_sizes, int n_in,
                              void* d_out, int out_size) {
    (void)in_sizes; (void)n_in; (void)out_size;

    const float* state    = (const float*)d_in[0];
    const float* language = (const float*)d_in[1];
    const float* Wv   = (const float*)d_in[6];
    const float* bv   = (const float*)d_in[7];
    const float* Wv2  = (const float*)d_in[12];
    const float* bv2  = (const float*)d_in[13];
    const float* Wo   = (const float*)d_in[14];
    const float* bo   = (const float*)d_in[15];
    const float* Wout = (const float*)d_in[16];
    const float* bout = (const float*)d_in[17];
    float* out = (float*)d_out;

    cudaFuncSetAttribute(fused_cma_kernel,
                         cudaFuncAttributeMaxDynamicSharedMemorySize,
                         SMEM_BYTES);

    unsigned* barp = nullptr;
    cudaGetSymbolAddress((void**)&barp, g_barrier);

    // Reset barrier counters each launch (async memset is graph-capturable).
    cudaMemsetAsync(barp, 0, sizeof(g_barrier));

    fused_cma_kernel<<<NB, NTHR, SMEM_BYTES>>>(state, language,
                                               Wv, bv, Wv2, bv2, Wo, bo,
                                               Wout, bout, out);
}